// round 1
// baseline (speedup 1.0000x reference)
#include <cuda_runtime.h>
#include <math.h>

#define BSZn   2
#define SEQn   512
#define DMODEL 768
#define DINNER 1536
#define NHEADSn 24
#define HEADDIMn 64
#define DSTATEn 64
#define CONVDIM 1664
#define DIP    3224
#define BT     (BSZn*SEQn)   // 1024
#define DFF    3072
#define EPSV   1e-5f

// ---------------- scratch (device globals; no allocation allowed) ----------------
__device__ float g_xn  [BT*DMODEL];
__device__ float g_zx  [BT*DIP];
__device__ float g_xbcf[BT*CONVDIM];
__device__ float g_xbcb[BT*CONVDIM];
__device__ float g_dtp [BT*NHEADSn];
__device__ float g_dAe [BT*NHEADSn];
__device__ float g_yf  [BT*DINNER];
__device__ float g_yb  [BT*DINNER];
__device__ float g_ysum[BT*DINNER];
__device__ float g_mi  [BT*DMODEL];
__device__ float g_m   [BT*DMODEL];
__device__ float g_h1  [BT*DFF];

// ---------------- helpers ----------------
__device__ __forceinline__ float warp_sum(float v) {
    #pragma unroll
    for (int o = 16; o > 0; o >>= 1) v += __shfl_xor_sync(0xffffffffu, v, o);
    return v;
}
__device__ __forceinline__ float siluf(float x) { return x / (1.f + expf(-x)); }
__device__ __forceinline__ float geluf(float x) { return 0.5f * x * (1.f + erff(x * 0.70710678118654752f)); }

// ---------------- LayerNorm (768) : 1 block/row, 256 thr ----------------
__global__ void ln_kernel(const float* __restrict__ in, const float* __restrict__ w,
                          const float* __restrict__ b, float* __restrict__ out) {
    int row = blockIdx.x;
    int tid = threadIdx.x;
    const float* x = in + (long)row * DMODEL;
    float v[3], s = 0.f, ss = 0.f;
    #pragma unroll
    for (int i = 0; i < 3; i++) {
        v[i] = x[tid + i * 256];
        s += v[i]; ss += v[i] * v[i];
    }
    __shared__ float sr[8], sr2[8], bres[2];
    float ws = warp_sum(s), ws2 = warp_sum(ss);
    int lane = tid & 31, wid = tid >> 5;
    if (lane == 0) { sr[wid] = ws; sr2[wid] = ws2; }
    __syncthreads();
    if (tid == 0) {
        float a = 0.f, c = 0.f;
        #pragma unroll
        for (int i = 0; i < 8; i++) { a += sr[i]; c += sr2[i]; }
        bres[0] = a; bres[1] = c;
    }
    __syncthreads();
    float mu  = bres[0] * (1.f / DMODEL);
    float var = bres[1] * (1.f / DMODEL) - mu * mu;
    float r = rsqrtf(var + EPSV);
    #pragma unroll
    for (int i = 0; i < 3; i++) {
        int c = tid + i * 256;
        out[(long)row * DMODEL + c] = (v[i] - mu) * r * w[c] + b[c];
    }
}

// ---------------- generic tiled GEMM: C[M,N] = A[M,K] @ W[N,K]^T -------------
// EPI: 0=none, 1=gelu(v+bias), 2=v+bias+resid
template<int EPI>
__global__ void gemm_kernel(const float* __restrict__ A, const float* __restrict__ W,
                            const float* __restrict__ bias, const float* __restrict__ resid,
                            float* __restrict__ C, int M, int N, int K) {
    const int BM = 64, BN = 64, BK = 16;
    __shared__ float As[BK][BM];
    __shared__ float Ws[BK][BN];
    int tx = threadIdx.x, ty = threadIdx.y;
    int tid = ty * 16 + tx;
    int row0 = blockIdx.y * BM;
    int col0 = blockIdx.x * BN;
    int lr  = tid >> 2;          // 0..63
    int lk4 = (tid & 3) << 2;    // 0,4,8,12
    float acc[4][4] = {};
    for (int k0 = 0; k0 < K; k0 += BK) {
        float4 av = *reinterpret_cast<const float4*>(&A[(long)(row0 + lr) * K + k0 + lk4]);
        As[lk4 + 0][lr] = av.x; As[lk4 + 1][lr] = av.y;
        As[lk4 + 2][lr] = av.z; As[lk4 + 3][lr] = av.w;
        int wn = col0 + lr;
        float4 wv = make_float4(0.f, 0.f, 0.f, 0.f);
        if (wn < N) wv = *reinterpret_cast<const float4*>(&W[(long)wn * K + k0 + lk4]);
        Ws[lk4 + 0][lr] = wv.x; Ws[lk4 + 1][lr] = wv.y;
        Ws[lk4 + 2][lr] = wv.z; Ws[lk4 + 3][lr] = wv.w;
        __syncthreads();
        #pragma unroll
        for (int k = 0; k < BK; k++) {
            float4 a = *reinterpret_cast<const float4*>(&As[k][ty * 4]);
            float4 w = *reinterpret_cast<const float4*>(&Ws[k][tx * 4]);
            float ar[4] = {a.x, a.y, a.z, a.w};
            float wr[4] = {w.x, w.y, w.z, w.w};
            #pragma unroll
            for (int i = 0; i < 4; i++)
                #pragma unroll
                for (int j = 0; j < 4; j++)
                    acc[i][j] += ar[i] * wr[j];
        }
        __syncthreads();
    }
    #pragma unroll
    for (int i = 0; i < 4; i++) {
        int row = row0 + ty * 4 + i;
        #pragma unroll
        for (int j = 0; j < 4; j++) {
            int col = col0 + tx * 4 + j;
            if (col < N) {
                float v = acc[i][j];
                if (EPI == 1) v = geluf(v + bias[col]);
                if (EPI == 2) v = v + bias[col] + resid[(long)row * N + col];
                C[(long)row * N + col] = v;
            }
        }
    }
}

// ---------------- depthwise causal conv (+anti-causal for backward) + SiLU ----
__global__ void conv_kernel(const float* __restrict__ zx, const float* __restrict__ cw,
                            const float* __restrict__ cb,
                            float* __restrict__ xf, float* __restrict__ xb) {
    long idx = (long)blockIdx.x * blockDim.x + threadIdx.x;
    if (idx >= (long)BT * CONVDIM) return;
    int c = (int)(idx % CONVDIM);
    long bt = idx / CONVDIM;
    int t = (int)(bt % SEQn);
    int b = (int)(bt / SEQn);
    float w0 = cw[c*4+0], w1 = cw[c*4+1], w2 = cw[c*4+2], w3 = cw[c*4+3];
    float bias = cb[c];
    const float* base = zx + ((long)b * SEQn) * DIP + DINNER + c;
    // forward: taps t-3..t with weights w0..w3
    float af = bias;
    if (t >= 3) af += w0 * base[(long)(t-3) * DIP];
    if (t >= 2) af += w1 * base[(long)(t-2) * DIP];
    if (t >= 1) af += w2 * base[(long)(t-1) * DIP];
    af += w3 * base[(long)t * DIP];
    xf[idx] = siluf(af);
    // backward: taps t+3..t with weights w0..w3
    float ab = bias;
    if (t + 3 < SEQn) ab += w0 * base[(long)(t+3) * DIP];
    if (t + 2 < SEQn) ab += w1 * base[(long)(t+2) * DIP];
    if (t + 1 < SEQn) ab += w2 * base[(long)(t+1) * DIP];
    ab += w3 * base[(long)t * DIP];
    xb[idx] = siluf(ab);
}

// ---------------- dt -> softplus, dA = exp(-exp(A_log)*dt) ----------------
__global__ void dt_kernel(const float* __restrict__ zx, const float* __restrict__ dt_bias,
                          const float* __restrict__ A_log,
                          float* __restrict__ dtp, float* __restrict__ dAe) {
    int idx = blockIdx.x * blockDim.x + threadIdx.x;
    if (idx >= BT * NHEADSn) return;
    int h = idx % NHEADSn;
    long row = idx / NHEADSn;
    float d = zx[row * DIP + DINNER + CONVDIM + h] + dt_bias[h];
    float sp = (d > 20.f) ? d : log1pf(expf(d));
    dtp[idx] = sp;
    dAe[idx] = expf(-expf(A_log[h]) * sp);
}

// ---------------- SSM sequential scan: 1 block per (dir,b,head), 64 thr -------
__global__ void scan_kernel(const float* __restrict__ xbcf, const float* __restrict__ xbcb,
                            const float* __restrict__ dtp, const float* __restrict__ dAe,
                            const float* __restrict__ Dp_,
                            float* __restrict__ yf, float* __restrict__ yb) {
    int blk = blockIdx.x;                 // dir*48 + b*24 + h
    int dir = blk / (BSZn * NHEADSn);
    int rem = blk % (BSZn * NHEADSn);
    int b = rem / NHEADSn, hh = rem % NHEADSn;
    const float* xBC = dir ? xbcb : xbcf;
    float* y = dir ? yb : yf;
    int p = threadIdx.x;                  // 0..63
    float hst[DSTATEn];
    #pragma unroll
    for (int n = 0; n < DSTATEn; n++) hst[n] = 0.f;
    __shared__ float sB[DSTATEn], sC[DSTATEn];
    __shared__ float sdt, sdA;
    float Dv = Dp_[hh];
    for (int step = 0; step < SEQn; step++) {
        int t = dir ? (SEQn - 1 - step) : step;
        long row = (long)b * SEQn + t;
        const float* xr = xBC + row * CONVDIM;
        sB[p] = xr[DINNER + p];
        sC[p] = xr[DINNER + DSTATEn + p];
        if (p == 0) {
            sdt = dtp[row * NHEADSn + hh];
            sdA = dAe[row * NHEADSn + hh];
        }
        __syncthreads();
        float xv = xr[hh * HEADDIMn + p];
        float c1 = sdt * xv;
        float a  = sdA;
        float yv = Dv * xv;
        #pragma unroll
        for (int n = 0; n < DSTATEn; n++) {
            hst[n] = a * hst[n] + c1 * sB[n];
            yv += hst[n] * sC[n];
        }
        y[row * DINNER + hh * HEADDIMn + p] = yv;
        __syncthreads();
    }
}

// ---------------- gate (silu z), per-direction RMSNorm, sum ----------------
__global__ void gatenorm_kernel(const float* __restrict__ yf, const float* __restrict__ yb,
                                const float* __restrict__ zx, const float* __restrict__ nw,
                                float* __restrict__ ysum) {
    int row = blockIdx.x;
    int tid = threadIdx.x;
    const float* z = zx + (long)row * DIP;
    float gf[6], gb[6], ssf = 0.f, ssb = 0.f;
    #pragma unroll
    for (int i = 0; i < 6; i++) {
        int c = tid + i * 256;
        float s = siluf(z[c]);
        float a = yf[(long)row * DINNER + c] * s;
        float d = yb[(long)row * DINNER + c] * s;
        gf[i] = a; gb[i] = d;
        ssf += a * a; ssb += d * d;
    }
    __shared__ float r1[8], r2[8], bres[2];
    float w1 = warp_sum(ssf), w2 = warp_sum(ssb);
    int lane = tid & 31, wid = tid >> 5;
    if (lane == 0) { r1[wid] = w1; r2[wid] = w2; }
    __syncthreads();
    if (tid == 0) {
        float a = 0.f, c = 0.f;
        #pragma unroll
        for (int i = 0; i < 8; i++) { a += r1[i]; c += r2[i]; }
        bres[0] = a; bres[1] = c;
    }
    __syncthreads();
    float rf = rsqrtf(bres[0] * (1.f / DINNER) + EPSV);
    float rb = rsqrtf(bres[1] * (1.f / DINNER) + EPSV);
    #pragma unroll
    for (int i = 0; i < 6; i++) {
        int c = tid + i * 256;
        ysum[(long)row * DINNER + c] = (gf[i] * rf + gb[i] * rb) * nw[c];
    }
}

// ---------------- launch ----------------
extern "C" void kernel_launch(void* const* d_in, const int* in_sizes, int n_in,
                              void* d_out, int out_size) {
    const float* x        = (const float*)d_in[0];
    const float* in_proj  = (const float*)d_in[1];
    const float* conv_w   = (const float*)d_in[2];
    const float* conv_b   = (const float*)d_in[3];
    const float* dt_bias  = (const float*)d_in[4];
    const float* A_log    = (const float*)d_in[5];
    const float* D_param  = (const float*)d_in[6];
    const float* norm_w   = (const float*)d_in[7];
    const float* out_proj = (const float*)d_in[8];
    const float* ln1_w    = (const float*)d_in[9];
    const float* ln1_b    = (const float*)d_in[10];
    const float* ln2_w    = (const float*)d_in[11];
    const float* ln2_b    = (const float*)d_in[12];
    const float* ff_w1    = (const float*)d_in[13];
    const float* ff_b1    = (const float*)d_in[14];
    const float* ff_w2    = (const float*)d_in[15];
    const float* ff_b2    = (const float*)d_in[16];
    float* out = (float*)d_out;

    float *p_xn, *p_zx, *p_xbcf, *p_xbcb, *p_dtp, *p_dAe, *p_yf, *p_yb, *p_ysum, *p_mi, *p_m, *p_h1;
    cudaGetSymbolAddress((void**)&p_xn,   g_xn);
    cudaGetSymbolAddress((void**)&p_zx,   g_zx);
    cudaGetSymbolAddress((void**)&p_xbcf, g_xbcf);
    cudaGetSymbolAddress((void**)&p_xbcb, g_xbcb);
    cudaGetSymbolAddress((void**)&p_dtp,  g_dtp);
    cudaGetSymbolAddress((void**)&p_dAe,  g_dAe);
    cudaGetSymbolAddress((void**)&p_yf,   g_yf);
    cudaGetSymbolAddress((void**)&p_yb,   g_yb);
    cudaGetSymbolAddress((void**)&p_ysum, g_ysum);
    cudaGetSymbolAddress((void**)&p_mi,   g_mi);
    cudaGetSymbolAddress((void**)&p_m,    g_m);
    cudaGetSymbolAddress((void**)&p_h1,   g_h1);

    dim3 tgemm(16, 16);

    // 1. ln1(x) -> xn
    ln_kernel<<<BT, 256>>>(x, ln1_w, ln1_b, p_xn);
    // 2. zxbcdt = xn @ in_proj^T   [1024, 3224]
    gemm_kernel<0><<<dim3((DIP + 63) / 64, BT / 64), tgemm>>>(p_xn, in_proj, nullptr, nullptr, p_zx, BT, DIP, DMODEL);
    // 3. conv + silu (both directions)
    {
        long tot = (long)BT * CONVDIM;
        conv_kernel<<<(int)((tot + 255) / 256), 256>>>(p_zx, conv_w, conv_b, p_xbcf, p_xbcb);
    }
    // 4. dt processing
    dt_kernel<<<(BT * NHEADSn + 255) / 256, 256>>>(p_zx, dt_bias, A_log, p_dtp, p_dAe);
    // 5. SSM scan (both directions)
    scan_kernel<<<2 * BSZn * NHEADSn, 64>>>(p_xbcf, p_xbcb, p_dtp, p_dAe, D_param, p_yf, p_yb);
    // 6. gate + RMSNorm per dir + sum
    gatenorm_kernel<<<BT, 256>>>(p_yf, p_yb, p_zx, norm_w, p_ysum);
    // 7. out_f + out_b = ysum @ out_proj^T  [1024, 768]
    gemm_kernel<0><<<dim3(DMODEL / 64, BT / 64), tgemm>>>(p_ysum, out_proj, nullptr, nullptr, p_mi, BT, DMODEL, DINNER);
    // 8. ln2
    ln_kernel<<<BT, 256>>>(p_mi, ln2_w, ln2_b, p_m);
    // 9. h1 = gelu(m @ ff_w1^T + b1)  [1024, 3072]
    gemm_kernel<1><<<dim3(DFF / 64, BT / 64), tgemm>>>(p_m, ff_w1, ff_b1, nullptr, p_h1, BT, DFF, DMODEL);
    // 10. out = h1 @ ff_w2^T + b2 + x
    gemm_kernel<2><<<dim3(DMODEL / 64, BT / 64), tgemm>>>(p_h1, ff_w2, ff_b2, x, out, BT, DMODEL, DFF);
}

// round 2
// speedup vs baseline: 1.2863x; 1.2863x over previous
#include <cuda_runtime.h>
#include <math.h>
#include <stdint.h>

#define BSZn   2
#define SEQn   512
#define DMODEL 768
#define DINNER 1536
#define NHEADSn 24
#define HEADDIMn 64
#define DSTATEn 64
#define CONVDIM 1664
#define DIP    3224
#define BT     (BSZn*SEQn)   // 1024
#define DFF    3072
#define EPSV   1e-5f

// ---------------- scratch ----------------
__device__ float g_xn  [BT*DMODEL];
__device__ float g_zx  [BT*DIP];
__device__ float g_xbcf[BT*CONVDIM];
__device__ float g_xbcb[BT*CONVDIM];
__device__ float g_dtp [BT*NHEADSn];
__device__ float g_dAe [BT*NHEADSn];
__device__ float g_yf  [BT*DINNER];
__device__ float g_yb  [BT*DINNER];
__device__ float g_ysum[BT*DINNER];
__device__ float g_mi  [BT*DMODEL];
__device__ float g_m   [BT*DMODEL];
__device__ float g_h1  [BT*DFF];

// ---------------- helpers ----------------
__device__ __forceinline__ float warp_sum(float v) {
    #pragma unroll
    for (int o = 16; o > 0; o >>= 1) v += __shfl_xor_sync(0xffffffffu, v, o);
    return v;
}
__device__ __forceinline__ float siluf(float x) { return x / (1.f + expf(-x)); }
__device__ __forceinline__ float geluf(float x) { return 0.5f * x * (1.f + erff(x * 0.70710678118654752f)); }

__device__ __forceinline__ uint32_t f2tf(float x) {
    uint32_t r;
    asm("cvt.rna.tf32.f32 %0, %1;" : "=r"(r) : "f"(x));
    return r;
}
// hi/lo split for 3xTF32
__device__ __forceinline__ void tf32_split(float x, uint32_t& hi, uint32_t& lo) {
    hi = f2tf(x);
    lo = f2tf(x - __uint_as_float(hi));
}
__device__ __forceinline__ void mma_tf32(float* c, const uint32_t* a, const uint32_t* b) {
    asm volatile(
        "mma.sync.aligned.m16n8k8.row.col.f32.tf32.tf32.f32 "
        "{%0,%1,%2,%3},{%4,%5,%6,%7},{%8,%9},{%0,%1,%2,%3};"
        : "+f"(c[0]), "+f"(c[1]), "+f"(c[2]), "+f"(c[3])
        : "r"(a[0]), "r"(a[1]), "r"(a[2]), "r"(a[3]), "r"(b[0]), "r"(b[1]));
}

// ---------------- LayerNorm ----------------
__global__ void ln_kernel(const float* __restrict__ in, const float* __restrict__ w,
                          const float* __restrict__ b, float* __restrict__ out) {
    int row = blockIdx.x;
    int tid = threadIdx.x;
    const float* x = in + (long)row * DMODEL;
    float v[3], s = 0.f, ss = 0.f;
    #pragma unroll
    for (int i = 0; i < 3; i++) {
        v[i] = x[tid + i * 256];
        s += v[i]; ss += v[i] * v[i];
    }
    __shared__ float sr[8], sr2[8], bres[2];
    float ws = warp_sum(s), ws2 = warp_sum(ss);
    int lane = tid & 31, wid = tid >> 5;
    if (lane == 0) { sr[wid] = ws; sr2[wid] = ws2; }
    __syncthreads();
    if (tid == 0) {
        float a = 0.f, c = 0.f;
        #pragma unroll
        for (int i = 0; i < 8; i++) { a += sr[i]; c += sr2[i]; }
        bres[0] = a; bres[1] = c;
    }
    __syncthreads();
    float mu  = bres[0] * (1.f / DMODEL);
    float var = bres[1] * (1.f / DMODEL) - mu * mu;
    float r = rsqrtf(var + EPSV);
    #pragma unroll
    for (int i = 0; i < 3; i++) {
        int c = tid + i * 256;
        out[(long)row * DMODEL + c] = (v[i] - mu) * r * w[c] + b[c];
    }
}

// ---------------- Tensor-core GEMM (3xTF32): C[M,N] = A[M,K] @ W[N,K]^T ------
// Block tile 128x64, BK=32, 256 threads (8 warps = 4M x 2N), warp tile 32x32.
// EPI: 0=none, 1=gelu(v+bias), 2=v+bias+resid
template<int EPI>
__global__ void __launch_bounds__(256) gemm_tc(
        const float* __restrict__ A, const float* __restrict__ W,
        const float* __restrict__ bias, const float* __restrict__ resid,
        float* __restrict__ C, int M, int N, int K) {
    const int BM = 128, BN = 64, BK = 32;
    __shared__ float As[BM][BK + 4];
    __shared__ float Ws[BN][BK + 4];
    int tid = threadIdx.x;
    int lane = tid & 31, wid = tid >> 5;
    int warpM = wid & 3;      // 0..3
    int warpN = wid >> 2;     // 0..1
    int row0 = blockIdx.y * BM;
    int col0 = blockIdx.x * BN;
    int g = lane >> 2, tg = lane & 3;

    float acc[2][4][4];
    #pragma unroll
    for (int mt = 0; mt < 2; mt++)
        #pragma unroll
        for (int nt = 0; nt < 4; nt++)
            #pragma unroll
            for (int i = 0; i < 4; i++) acc[mt][nt][i] = 0.f;

    int lr = tid >> 3;           // 0..31
    int lc4 = (tid & 7) * 4;     // 0..28

    for (int k0 = 0; k0 < K; k0 += BK) {
        // load A: 128x32
        #pragma unroll
        for (int i = 0; i < 4; i++) {
            int r = lr + i * 32;
            float4 v = *reinterpret_cast<const float4*>(&A[(long)(row0 + r) * K + k0 + lc4]);
            As[r][lc4 + 0] = v.x; As[r][lc4 + 1] = v.y;
            As[r][lc4 + 2] = v.z; As[r][lc4 + 3] = v.w;
        }
        // load W: 64x32 (guard rows)
        #pragma unroll
        for (int i = 0; i < 2; i++) {
            int r = lr + i * 32;
            int n = col0 + r;
            float4 v = make_float4(0.f, 0.f, 0.f, 0.f);
            if (n < N) v = *reinterpret_cast<const float4*>(&W[(long)n * K + k0 + lc4]);
            Ws[r][lc4 + 0] = v.x; Ws[r][lc4 + 1] = v.y;
            Ws[r][lc4 + 2] = v.z; Ws[r][lc4 + 3] = v.w;
        }
        __syncthreads();
        #pragma unroll
        for (int kk = 0; kk < BK; kk += 8) {
            uint32_t ah[2][4], al[2][4], bh[4][2], bl[4][2];
            #pragma unroll
            for (int mt = 0; mt < 2; mt++) {
                int m = warpM * 32 + mt * 16;
                tf32_split(As[m + g    ][kk + tg    ], ah[mt][0], al[mt][0]);
                tf32_split(As[m + g + 8][kk + tg    ], ah[mt][1], al[mt][1]);
                tf32_split(As[m + g    ][kk + tg + 4], ah[mt][2], al[mt][2]);
                tf32_split(As[m + g + 8][kk + tg + 4], ah[mt][3], al[mt][3]);
            }
            #pragma unroll
            for (int nt = 0; nt < 4; nt++) {
                int n = warpN * 32 + nt * 8;
                tf32_split(Ws[n + g][kk + tg    ], bh[nt][0], bl[nt][0]);
                tf32_split(Ws[n + g][kk + tg + 4], bh[nt][1], bl[nt][1]);
            }
            #pragma unroll
            for (int mt = 0; mt < 2; mt++)
                #pragma unroll
                for (int nt = 0; nt < 4; nt++) {
                    mma_tf32(acc[mt][nt], ah[mt], bl[nt]);
                    mma_tf32(acc[mt][nt], al[mt], bh[nt]);
                    mma_tf32(acc[mt][nt], ah[mt], bh[nt]);
                }
        }
        __syncthreads();
    }

    // epilogue: c0 (g, tg*2), c1 (g, tg*2+1), c2 (g+8, tg*2), c3 (g+8, tg*2+1)
    #pragma unroll
    for (int mt = 0; mt < 2; mt++) {
        int rbase = row0 + warpM * 32 + mt * 16 + g;
        #pragma unroll
        for (int nt = 0; nt < 4; nt++) {
            int cbase = col0 + warpN * 32 + nt * 8 + tg * 2;
            #pragma unroll
            for (int i = 0; i < 4; i++) {
                int row = rbase + (i >> 1) * 8;
                int col = cbase + (i & 1);
                if (col < N) {
                    float v = acc[mt][nt][i];
                    if (EPI == 1) v = geluf(v + bias[col]);
                    if (EPI == 2) v = v + bias[col] + resid[(long)row * N + col];
                    C[(long)row * N + col] = v;
                }
            }
        }
    }
}

// ---------------- depthwise conv (causal fwd + anti-causal bwd) + SiLU --------
__global__ void conv_kernel(const float* __restrict__ zx, const float* __restrict__ cw,
                            const float* __restrict__ cb,
                            float* __restrict__ xf, float* __restrict__ xb) {
    long idx = (long)blockIdx.x * blockDim.x + threadIdx.x;
    if (idx >= (long)BT * CONVDIM) return;
    int c = (int)(idx % CONVDIM);
    long bt = idx / CONVDIM;
    int t = (int)(bt % SEQn);
    int b = (int)(bt / SEQn);
    float w0 = cw[c*4+0], w1 = cw[c*4+1], w2 = cw[c*4+2], w3 = cw[c*4+3];
    float bias = cb[c];
    const float* base = zx + ((long)b * SEQn) * DIP + DINNER + c;
    float af = bias;
    if (t >= 3) af += w0 * base[(long)(t-3) * DIP];
    if (t >= 2) af += w1 * base[(long)(t-2) * DIP];
    if (t >= 1) af += w2 * base[(long)(t-1) * DIP];
    af += w3 * base[(long)t * DIP];
    xf[idx] = siluf(af);
    float ab = bias;
    if (t + 3 < SEQn) ab += w0 * base[(long)(t+3) * DIP];
    if (t + 2 < SEQn) ab += w1 * base[(long)(t+2) * DIP];
    if (t + 1 < SEQn) ab += w2 * base[(long)(t+1) * DIP];
    ab += w3 * base[(long)t * DIP];
    xb[idx] = siluf(ab);
}

// ---------------- dt processing ----------------
__global__ void dt_kernel(const float* __restrict__ zx, const float* __restrict__ dt_bias,
                          const float* __restrict__ A_log,
                          float* __restrict__ dtp, float* __restrict__ dAe) {
    int idx = blockIdx.x * blockDim.x + threadIdx.x;
    if (idx >= BT * NHEADSn) return;
    int h = idx % NHEADSn;
    long row = idx / NHEADSn;
    float d = zx[row * DIP + DINNER + CONVDIM + h] + dt_bias[h];
    float sp = (d > 20.f) ? d : log1pf(expf(d));
    dtp[idx] = sp;
    dAe[idx] = expf(-expf(A_log[h]) * sp);
}

// ---------------- SSM scan ----------------
__global__ void scan_kernel(const float* __restrict__ xbcf, const float* __restrict__ xbcb,
                            const float* __restrict__ dtp, const float* __restrict__ dAe,
                            const float* __restrict__ Dp_,
                            float* __restrict__ yf, float* __restrict__ yb) {
    int blk = blockIdx.x;
    int dir = blk / (BSZn * NHEADSn);
    int rem = blk % (BSZn * NHEADSn);
    int b = rem / NHEADSn, hh = rem % NHEADSn;
    const float* xBC = dir ? xbcb : xbcf;
    float* y = dir ? yb : yf;
    int p = threadIdx.x;
    float hst[DSTATEn];
    #pragma unroll
    for (int n = 0; n < DSTATEn; n++) hst[n] = 0.f;
    __shared__ float sB[DSTATEn], sC[DSTATEn];
    __shared__ float sdt, sdA;
    float Dv = Dp_[hh];
    for (int step = 0; step < SEQn; step++) {
        int t = dir ? (SEQn - 1 - step) : step;
        long row = (long)b * SEQn + t;
        const float* xr = xBC + row * CONVDIM;
        sB[p] = xr[DINNER + p];
        sC[p] = xr[DINNER + DSTATEn + p];
        if (p == 0) {
            sdt = dtp[row * NHEADSn + hh];
            sdA = dAe[row * NHEADSn + hh];
        }
        __syncthreads();
        float xv = xr[hh * HEADDIMn + p];
        float c1 = sdt * xv;
        float a  = sdA;
        float yv = Dv * xv;
        #pragma unroll
        for (int n = 0; n < DSTATEn; n++) {
            hst[n] = a * hst[n] + c1 * sB[n];
            yv += hst[n] * sC[n];
        }
        y[row * DINNER + hh * HEADDIMn + p] = yv;
        __syncthreads();
    }
}

// ---------------- gate + RMSNorm + sum ----------------
__global__ void gatenorm_kernel(const float* __restrict__ yf, const float* __restrict__ yb,
                                const float* __restrict__ zx, const float* __restrict__ nw,
                                float* __restrict__ ysum) {
    int row = blockIdx.x;
    int tid = threadIdx.x;
    const float* z = zx + (long)row * DIP;
    float gf[6], gb[6], ssf = 0.f, ssb = 0.f;
    #pragma unroll
    for (int i = 0; i < 6; i++) {
        int c = tid + i * 256;
        float s = siluf(z[c]);
        float a = yf[(long)row * DINNER + c] * s;
        float d = yb[(long)row * DINNER + c] * s;
        gf[i] = a; gb[i] = d;
        ssf += a * a; ssb += d * d;
    }
    __shared__ float r1[8], r2[8], bres[2];
    float w1 = warp_sum(ssf), w2 = warp_sum(ssb);
    int lane = tid & 31, wid = tid >> 5;
    if (lane == 0) { r1[wid] = w1; r2[wid] = w2; }
    __syncthreads();
    if (tid == 0) {
        float a = 0.f, c = 0.f;
        #pragma unroll
        for (int i = 0; i < 8; i++) { a += r1[i]; c += r2[i]; }
        bres[0] = a; bres[1] = c;
    }
    __syncthreads();
    float rf = rsqrtf(bres[0] * (1.f / DINNER) + EPSV);
    float rb = rsqrtf(bres[1] * (1.f / DINNER) + EPSV);
    #pragma unroll
    for (int i = 0; i < 6; i++) {
        int c = tid + i * 256;
        ysum[(long)row * DINNER + c] = (gf[i] * rf + gb[i] * rb) * nw[c];
    }
}

// ---------------- launch ----------------
extern "C" void kernel_launch(void* const* d_in, const int* in_sizes, int n_in,
                              void* d_out, int out_size) {
    const float* x        = (const float*)d_in[0];
    const float* in_proj  = (const float*)d_in[1];
    const float* conv_w   = (const float*)d_in[2];
    const float* conv_b   = (const float*)d_in[3];
    const float* dt_bias  = (const float*)d_in[4];
    const float* A_log    = (const float*)d_in[5];
    const float* D_param  = (const float*)d_in[6];
    const float* norm_w   = (const float*)d_in[7];
    const float* out_proj = (const float*)d_in[8];
    const float* ln1_w    = (const float*)d_in[9];
    const float* ln1_b    = (const float*)d_in[10];
    const float* ln2_w    = (const float*)d_in[11];
    const float* ln2_b    = (const float*)d_in[12];
    const float* ff_w1    = (const float*)d_in[13];
    const float* ff_b1    = (const float*)d_in[14];
    const float* ff_w2    = (const float*)d_in[15];
    const float* ff_b2    = (const float*)d_in[16];
    float* out = (float*)d_out;

    float *p_xn, *p_zx, *p_xbcf, *p_xbcb, *p_dtp, *p_dAe, *p_yf, *p_yb, *p_ysum, *p_mi, *p_m, *p_h1;
    cudaGetSymbolAddress((void**)&p_xn,   g_xn);
    cudaGetSymbolAddress((void**)&p_zx,   g_zx);
    cudaGetSymbolAddress((void**)&p_xbcf, g_xbcf);
    cudaGetSymbolAddress((void**)&p_xbcb, g_xbcb);
    cudaGetSymbolAddress((void**)&p_dtp,  g_dtp);
    cudaGetSymbolAddress((void**)&p_dAe,  g_dAe);
    cudaGetSymbolAddress((void**)&p_yf,   g_yf);
    cudaGetSymbolAddress((void**)&p_yb,   g_yb);
    cudaGetSymbolAddress((void**)&p_ysum, g_ysum);
    cudaGetSymbolAddress((void**)&p_mi,   g_mi);
    cudaGetSymbolAddress((void**)&p_m,    g_m);
    cudaGetSymbolAddress((void**)&p_h1,   g_h1);

    // 1. ln1(x) -> xn
    ln_kernel<<<BT, 256>>>(x, ln1_w, ln1_b, p_xn);
    // 2. zxbcdt = xn @ in_proj^T   [1024, 3224]
    gemm_tc<0><<<dim3((DIP + 63) / 64, BT / 128), 256>>>(p_xn, in_proj, nullptr, nullptr, p_zx, BT, DIP, DMODEL);
    // 3. conv + silu (both directions)
    {
        long tot = (long)BT * CONVDIM;
        conv_kernel<<<(int)((tot + 255) / 256), 256>>>(p_zx, conv_w, conv_b, p_xbcf, p_xbcb);
    }
    // 4. dt processing
    dt_kernel<<<(BT * NHEADSn + 255) / 256, 256>>>(p_zx, dt_bias, A_log, p_dtp, p_dAe);
    // 5. SSM scan (both directions)
    scan_kernel<<<2 * BSZn * NHEADSn, 64>>>(p_xbcf, p_xbcb, p_dtp, p_dAe, D_param, p_yf, p_yb);
    // 6. gate + RMSNorm per dir + sum
    gatenorm_kernel<<<BT, 256>>>(p_yf, p_yb, p_zx, norm_w, p_ysum);
    // 7. out_f + out_b = ysum @ out_proj^T  [1024, 768]
    gemm_tc<0><<<dim3(DMODEL / 64, BT / 128), 256>>>(p_ysum, out_proj, nullptr, nullptr, p_mi, BT, DMODEL, DINNER);
    // 8. ln2
    ln_kernel<<<BT, 256>>>(p_mi, ln2_w, ln2_b, p_m);
    // 9. h1 = gelu(m @ ff_w1^T + b1)  [1024, 3072]
    gemm_tc<1><<<dim3(DFF / 64, BT / 128), 256>>>(p_m, ff_w1, ff_b1, nullptr, p_h1, BT, DFF, DMODEL);
    // 10. out = h1 @ ff_w2^T + b2 + x
    gemm_tc<2><<<dim3(DMODEL / 64, BT / 128), 256>>>(p_h1, ff_w2, ff_b2, x, out, BT, DMODEL, DFF);
}

// round 3
// speedup vs baseline: 1.7693x; 1.3755x over previous
#include <cuda_runtime.h>
#include <cuda_bf16.h>
#include <math.h>
#include <stdint.h>

#define BSZn   2
#define SEQn   512
#define DMODEL 768
#define DINNER 1536
#define NHEADSn 24
#define HEADDIMn 64
#define DSTATEn 64
#define CONVDIM 1664
#define DIP    3224
#define BT     (BSZn*SEQn)   // 1024
#define DFF    3072
#define EPSV   1e-5f

// ---------------- scratch ----------------
__device__ float g_xn  [BT*DMODEL];
__device__ float g_zx  [BT*DIP];
__device__ float g_xbcf[BT*CONVDIM];
__device__ float g_xbcb[BT*CONVDIM];
__device__ float g_dtp [BT*NHEADSn];
__device__ float g_dAe [BT*NHEADSn];
__device__ float g_yf  [BT*DINNER];
__device__ float g_yb  [BT*DINNER];
__device__ float g_ysum[BT*DINNER];
__device__ float g_mi  [BT*DMODEL];
__device__ float g_m   [BT*DMODEL];
__device__ float g_h1  [BT*DFF];

// ---------------- helpers ----------------
__device__ __forceinline__ float warp_sum(float v) {
    #pragma unroll
    for (int o = 16; o > 0; o >>= 1) v += __shfl_xor_sync(0xffffffffu, v, o);
    return v;
}
__device__ __forceinline__ float siluf(float x) { return x / (1.f + expf(-x)); }
__device__ __forceinline__ float geluf(float x) { return 0.5f * x * (1.f + erff(x * 0.70710678118654752f)); }

__device__ __forceinline__ uint32_t pack_bf2(float lo_elem, float hi_elem) {
    __nv_bfloat162 h = __floats2bfloat162_rn(lo_elem, hi_elem); // .x = first (low 16 bits)
    return *reinterpret_cast<uint32_t*>(&h);
}

__device__ __forceinline__ void mma_bf16(float* c, const uint32_t* a, const uint32_t* b) {
    asm volatile(
        "mma.sync.aligned.m16n8k16.row.col.f32.bf16.bf16.f32 "
        "{%0,%1,%2,%3},{%4,%5,%6,%7},{%8,%9},{%0,%1,%2,%3};"
        : "+f"(c[0]), "+f"(c[1]), "+f"(c[2]), "+f"(c[3])
        : "r"(a[0]), "r"(a[1]), "r"(a[2]), "r"(a[3]), "r"(b[0]), "r"(b[1]));
}

// ---------------- LayerNorm ----------------
__global__ void ln_kernel(const float* __restrict__ in, const float* __restrict__ w,
                          const float* __restrict__ b, float* __restrict__ out) {
    int row = blockIdx.x;
    int tid = threadIdx.x;
    const float* x = in + (long)row * DMODEL;
    float v[3], s = 0.f, ss = 0.f;
    #pragma unroll
    for (int i = 0; i < 3; i++) {
        v[i] = x[tid + i * 256];
        s += v[i]; ss += v[i] * v[i];
    }
    __shared__ float sr[8], sr2[8], bres[2];
    float ws = warp_sum(s), ws2 = warp_sum(ss);
    int lane = tid & 31, wid = tid >> 5;
    if (lane == 0) { sr[wid] = ws; sr2[wid] = ws2; }
    __syncthreads();
    if (tid == 0) {
        float a = 0.f, c = 0.f;
        #pragma unroll
        for (int i = 0; i < 8; i++) { a += sr[i]; c += sr2[i]; }
        bres[0] = a; bres[1] = c;
    }
    __syncthreads();
    float mu  = bres[0] * (1.f / DMODEL);
    float var = bres[1] * (1.f / DMODEL) - mu * mu;
    float r = rsqrtf(var + EPSV);
    #pragma unroll
    for (int i = 0; i < 3; i++) {
        int c = tid + i * 256;
        out[(long)row * DMODEL + c] = (v[i] - mu) * r * w[c] + b[c];
    }
}

// ------------- Tensor-core GEMM (bf16 hi/lo 3-product): C = A @ W^T ----------
// Block tile 128x64, BK=32, 256 thr (8 warps = 4M x 2N), warp tile 32x32.
// smem: pre-split bf16 hi/lo planes, stride 40 elems (conflict-free).
// EPI: 0=none, 1=gelu(v+bias), 2=v+bias+resid
#define GLDS 40   // smem row stride in bf16 elements
template<int EPI>
__global__ void __launch_bounds__(256) gemm_tc(
        const float* __restrict__ A, const float* __restrict__ W,
        const float* __restrict__ bias, const float* __restrict__ resid,
        float* __restrict__ C, int M, int N, int K) {
    const int BM = 128, BN = 64, BK = 32;
    // uint32 views: pair index = (row*GLDS + col)/2
    __shared__ uint32_t Ah32[BM * GLDS / 2], Al32[BM * GLDS / 2];
    __shared__ uint32_t Wh32[BN * GLDS / 2], Wl32[BN * GLDS / 2];
    int tid = threadIdx.x;
    int lane = tid & 31, wid = tid >> 5;
    int warpM = wid & 3;      // 0..3
    int warpN = wid >> 2;     // 0..1
    int row0 = blockIdx.y * BM;
    int col0 = blockIdx.x * BN;
    int g = lane >> 2, tg = lane & 3;

    float acc[2][4][4];
    #pragma unroll
    for (int mt = 0; mt < 2; mt++)
        #pragma unroll
        for (int nt = 0; nt < 4; nt++)
            #pragma unroll
            for (int i = 0; i < 4; i++) acc[mt][nt][i] = 0.f;

    int lr = tid >> 3;           // 0..31
    int lc4 = (tid & 7) * 4;     // 0..28
    int pbase = lr * (GLDS / 2) + (lc4 >> 1); // pair index base for stores

    // prefetch tile 0
    float4 pa[4]; float4 pw[2];
    #pragma unroll
    for (int i = 0; i < 4; i++)
        pa[i] = *reinterpret_cast<const float4*>(&A[(long)(row0 + lr + i * 32) * K + lc4]);
    #pragma unroll
    for (int i = 0; i < 2; i++) {
        int n = col0 + lr + i * 32;
        pw[i] = make_float4(0.f, 0.f, 0.f, 0.f);
        if (n < N) pw[i] = *reinterpret_cast<const float4*>(&W[(long)n * K + lc4]);
    }

    for (int k0 = 0; k0 < K; k0 += BK) {
        // convert + store current tile
        #pragma unroll
        for (int i = 0; i < 4; i++) {
            float vv[4] = {pa[i].x, pa[i].y, pa[i].z, pa[i].w};
            float h[4], l[4];
            #pragma unroll
            for (int j = 0; j < 4; j++) {
                h[j] = __bfloat162float(__float2bfloat16_rn(vv[j]));
                l[j] = vv[j] - h[j];
            }
            int pidx = pbase + i * 32 * (GLDS / 2);
            Ah32[pidx]     = pack_bf2(h[0], h[1]);
            Ah32[pidx + 1] = pack_bf2(h[2], h[3]);
            Al32[pidx]     = pack_bf2(l[0], l[1]);
            Al32[pidx + 1] = pack_bf2(l[2], l[3]);
        }
        #pragma unroll
        for (int i = 0; i < 2; i++) {
            float vv[4] = {pw[i].x, pw[i].y, pw[i].z, pw[i].w};
            float h[4], l[4];
            #pragma unroll
            for (int j = 0; j < 4; j++) {
                h[j] = __bfloat162float(__float2bfloat16_rn(vv[j]));
                l[j] = vv[j] - h[j];
            }
            int pidx = pbase + i * 32 * (GLDS / 2);
            Wh32[pidx]     = pack_bf2(h[0], h[1]);
            Wh32[pidx + 1] = pack_bf2(h[2], h[3]);
            Wl32[pidx]     = pack_bf2(l[0], l[1]);
            Wl32[pidx + 1] = pack_bf2(l[2], l[3]);
        }
        __syncthreads();

        // prefetch next tile (overlaps with compute below)
        if (k0 + BK < K) {
            int kn = k0 + BK;
            #pragma unroll
            for (int i = 0; i < 4; i++)
                pa[i] = *reinterpret_cast<const float4*>(&A[(long)(row0 + lr + i * 32) * K + kn + lc4]);
            #pragma unroll
            for (int i = 0; i < 2; i++) {
                int n = col0 + lr + i * 32;
                pw[i] = make_float4(0.f, 0.f, 0.f, 0.f);
                if (n < N) pw[i] = *reinterpret_cast<const float4*>(&W[(long)n * K + kn + lc4]);
            }
        }

        // compute: 2 k-slabs of 16
        #pragma unroll
        for (int ks = 0; ks < 2; ks++) {
            int kk2 = ks * 8;  // pair offset
            uint32_t ah[2][4], al[2][4], bh[4][2], bl[4][2];
            #pragma unroll
            for (int mt = 0; mt < 2; mt++) {
                int m = warpM * 32 + mt * 16;
                int r0i = (m + g) * (GLDS / 2) + kk2 + tg;
                int r1i = (m + g + 8) * (GLDS / 2) + kk2 + tg;
                ah[mt][0] = Ah32[r0i];     al[mt][0] = Al32[r0i];
                ah[mt][1] = Ah32[r1i];     al[mt][1] = Al32[r1i];
                ah[mt][2] = Ah32[r0i + 4]; al[mt][2] = Al32[r0i + 4];
                ah[mt][3] = Ah32[r1i + 4]; al[mt][3] = Al32[r1i + 4];
            }
            #pragma unroll
            for (int nt = 0; nt < 4; nt++) {
                int n = warpN * 32 + nt * 8 + g;
                int ni = n * (GLDS / 2) + kk2 + tg;
                bh[nt][0] = Wh32[ni];     bl[nt][0] = Wl32[ni];
                bh[nt][1] = Wh32[ni + 4]; bl[nt][1] = Wl32[ni + 4];
            }
            #pragma unroll
            for (int mt = 0; mt < 2; mt++)
                #pragma unroll
                for (int nt = 0; nt < 4; nt++) {
                    mma_bf16(acc[mt][nt], ah[mt], bl[nt]);
                    mma_bf16(acc[mt][nt], al[mt], bh[nt]);
                    mma_bf16(acc[mt][nt], ah[mt], bh[nt]);
                }
        }
        __syncthreads();
    }

    // epilogue: c0 (g, 2tg), c1 (g, 2tg+1), c2 (g+8, 2tg), c3 (g+8, 2tg+1)
    #pragma unroll
    for (int mt = 0; mt < 2; mt++) {
        int rbase = row0 + warpM * 32 + mt * 16 + g;
        #pragma unroll
        for (int nt = 0; nt < 4; nt++) {
            int cbase = col0 + warpN * 32 + nt * 8 + tg * 2;
            #pragma unroll
            for (int i = 0; i < 4; i++) {
                int row = rbase + (i >> 1) * 8;
                int col = cbase + (i & 1);
                if (col < N) {
                    float v = acc[mt][nt][i];
                    if (EPI == 1) v = geluf(v + bias[col]);
                    if (EPI == 2) v = v + bias[col] + resid[(long)row * N + col];
                    C[(long)row * N + col] = v;
                }
            }
        }
    }
}

// ---------------- depthwise conv (causal fwd + anti-causal bwd) + SiLU --------
__global__ void conv_kernel(const float* __restrict__ zx, const float* __restrict__ cw,
                            const float* __restrict__ cb,
                            float* __restrict__ xf, float* __restrict__ xb) {
    long idx = (long)blockIdx.x * blockDim.x + threadIdx.x;
    if (idx >= (long)BT * CONVDIM) return;
    int c = (int)(idx % CONVDIM);
    long bt = idx / CONVDIM;
    int t = (int)(bt % SEQn);
    int b = (int)(bt / SEQn);
    float w0 = cw[c*4+0], w1 = cw[c*4+1], w2 = cw[c*4+2], w3 = cw[c*4+3];
    float bias = cb[c];
    const float* base = zx + ((long)b * SEQn) * DIP + DINNER + c;
    float af = bias;
    if (t >= 3) af += w0 * base[(long)(t-3) * DIP];
    if (t >= 2) af += w1 * base[(long)(t-2) * DIP];
    if (t >= 1) af += w2 * base[(long)(t-1) * DIP];
    af += w3 * base[(long)t * DIP];
    xf[idx] = siluf(af);
    float ab = bias;
    if (t + 3 < SEQn) ab += w0 * base[(long)(t+3) * DIP];
    if (t + 2 < SEQn) ab += w1 * base[(long)(t+2) * DIP];
    if (t + 1 < SEQn) ab += w2 * base[(long)(t+1) * DIP];
    ab += w3 * base[(long)t * DIP];
    xb[idx] = siluf(ab);
}

// ---------------- dt processing ----------------
__global__ void dt_kernel(const float* __restrict__ zx, const float* __restrict__ dt_bias,
                          const float* __restrict__ A_log,
                          float* __restrict__ dtp, float* __restrict__ dAe) {
    int idx = blockIdx.x * blockDim.x + threadIdx.x;
    if (idx >= BT * NHEADSn) return;
    int h = idx % NHEADSn;
    long row = idx / NHEADSn;
    float d = zx[row * DIP + DINNER + CONVDIM + h] + dt_bias[h];
    float sp = (d > 20.f) ? d : log1pf(expf(d));
    dtp[idx] = sp;
    dAe[idx] = expf(-expf(A_log[h]) * sp);
}

// ---------------- SSM scan (prefetch + double-buffered smem, 1 bar/step) -----
__global__ void scan_kernel(const float* __restrict__ xbcf, const float* __restrict__ xbcb,
                            const float* __restrict__ dtp, const float* __restrict__ dAe,
                            const float* __restrict__ Dp_,
                            float* __restrict__ yf, float* __restrict__ yb) {
    int blk = blockIdx.x;
    int dir = blk / (BSZn * NHEADSn);
    int rem = blk % (BSZn * NHEADSn);
    int b = rem / NHEADSn, hh = rem % NHEADSn;
    const float* xBC = dir ? xbcb : xbcf;
    float* y = dir ? yb : yf;
    int p = threadIdx.x;
    float hst[DSTATEn];
    #pragma unroll
    for (int n = 0; n < DSTATEn; n++) hst[n] = 0.f;
    __shared__ float sB[2][DSTATEn], sC[2][DSTATEn];
    float Dv = Dp_[hh];

    // prefetch step 0
    int t = dir ? (SEQn - 1) : 0;
    long row = (long)b * SEQn + t;
    const float* xr = xBC + row * CONVDIM;
    float nB = xr[DINNER + p];
    float nC = xr[DINNER + DSTATEn + p];
    float nx = xr[hh * HEADDIMn + p];
    float ndt = dtp[row * NHEADSn + hh];
    float ndA = dAe[row * NHEADSn + hh];

    for (int step = 0; step < SEQn; step++) {
        int buf = step & 1;
        sB[buf][p] = nB; sC[buf][p] = nC;
        float cx = nx, cdt = ndt, cdA = ndA;
        long crow = row;
        __syncthreads();
        if (step + 1 < SEQn) {
            int t2 = dir ? (SEQn - 2 - step) : (step + 1);
            row = (long)b * SEQn + t2;
            const float* xr2 = xBC + row * CONVDIM;
            nB = xr2[DINNER + p];
            nC = xr2[DINNER + DSTATEn + p];
            nx = xr2[hh * HEADDIMn + p];
            ndt = dtp[row * NHEADSn + hh];
            ndA = dAe[row * NHEADSn + hh];
        }
        float c1 = cdt * cx;
        float yv = Dv * cx;
        #pragma unroll
        for (int n = 0; n < DSTATEn; n++) {
            hst[n] = cdA * hst[n] + c1 * sB[buf][n];
            yv += hst[n] * sC[buf][n];
        }
        y[crow * DINNER + hh * HEADDIMn + p] = yv;
    }
}

// ---------------- gate + RMSNorm + sum ----------------
__global__ void gatenorm_kernel(const float* __restrict__ yf, const float* __restrict__ yb,
                                const float* __restrict__ zx, const float* __restrict__ nw,
                                float* __restrict__ ysum) {
    int row = blockIdx.x;
    int tid = threadIdx.x;
    const float* z = zx + (long)row * DIP;
    float gf[6], gb[6], ssf = 0.f, ssb = 0.f;
    #pragma unroll
    for (int i = 0; i < 6; i++) {
        int c = tid + i * 256;
        float s = siluf(z[c]);
        float a = yf[(long)row * DINNER + c] * s;
        float d = yb[(long)row * DINNER + c] * s;
        gf[i] = a; gb[i] = d;
        ssf += a * a; ssb += d * d;
    }
    __shared__ float r1[8], r2[8], bres[2];
    float w1 = warp_sum(ssf), w2 = warp_sum(ssb);
    int lane = tid & 31, wid = tid >> 5;
    if (lane == 0) { r1[wid] = w1; r2[wid] = w2; }
    __syncthreads();
    if (tid == 0) {
        float a = 0.f, c = 0.f;
        #pragma unroll
        for (int i = 0; i < 8; i++) { a += r1[i]; c += r2[i]; }
        bres[0] = a; bres[1] = c;
    }
    __syncthreads();
    float rf = rsqrtf(bres[0] * (1.f / DINNER) + EPSV);
    float rb = rsqrtf(bres[1] * (1.f / DINNER) + EPSV);
    #pragma unroll
    for (int i = 0; i < 6; i++) {
        int c = tid + i * 256;
        ysum[(long)row * DINNER + c] = (gf[i] * rf + gb[i] * rb) * nw[c];
    }
}

// ---------------- launch ----------------
extern "C" void kernel_launch(void* const* d_in, const int* in_sizes, int n_in,
                              void* d_out, int out_size) {
    const float* x        = (const float*)d_in[0];
    const float* in_proj  = (const float*)d_in[1];
    const float* conv_w   = (const float*)d_in[2];
    const float* conv_b   = (const float*)d_in[3];
    const float* dt_bias  = (const float*)d_in[4];
    const float* A_log    = (const float*)d_in[5];
    const float* D_param  = (const float*)d_in[6];
    const float* norm_w   = (const float*)d_in[7];
    const float* out_proj = (const float*)d_in[8];
    const float* ln1_w    = (const float*)d_in[9];
    const float* ln1_b    = (const float*)d_in[10];
    const float* ln2_w    = (const float*)d_in[11];
    const float* ln2_b    = (const float*)d_in[12];
    const float* ff_w1    = (const float*)d_in[13];
    const float* ff_b1    = (const float*)d_in[14];
    const float* ff_w2    = (const float*)d_in[15];
    const float* ff_b2    = (const float*)d_in[16];
    float* out = (float*)d_out;

    float *p_xn, *p_zx, *p_xbcf, *p_xbcb, *p_dtp, *p_dAe, *p_yf, *p_yb, *p_ysum, *p_mi, *p_m, *p_h1;
    cudaGetSymbolAddress((void**)&p_xn,   g_xn);
    cudaGetSymbolAddress((void**)&p_zx,   g_zx);
    cudaGetSymbolAddress((void**)&p_xbcf, g_xbcf);
    cudaGetSymbolAddress((void**)&p_xbcb, g_xbcb);
    cudaGetSymbolAddress((void**)&p_dtp,  g_dtp);
    cudaGetSymbolAddress((void**)&p_dAe,  g_dAe);
    cudaGetSymbolAddress((void**)&p_yf,   g_yf);
    cudaGetSymbolAddress((void**)&p_yb,   g_yb);
    cudaGetSymbolAddress((void**)&p_ysum, g_ysum);
    cudaGetSymbolAddress((void**)&p_mi,   g_mi);
    cudaGetSymbolAddress((void**)&p_m,    g_m);
    cudaGetSymbolAddress((void**)&p_h1,   g_h1);

    // 1. ln1(x) -> xn
    ln_kernel<<<BT, 256>>>(x, ln1_w, ln1_b, p_xn);
    // 2. zxbcdt = xn @ in_proj^T   [1024, 3224]
    gemm_tc<0><<<dim3((DIP + 63) / 64, BT / 128), 256>>>(p_xn, in_proj, nullptr, nullptr, p_zx, BT, DIP, DMODEL);
    // 3. conv + silu (both directions)
    {
        long tot = (long)BT * CONVDIM;
        conv_kernel<<<(int)((tot + 255) / 256), 256>>>(p_zx, conv_w, conv_b, p_xbcf, p_xbcb);
    }
    // 4. dt processing
    dt_kernel<<<(BT * NHEADSn + 255) / 256, 256>>>(p_zx, dt_bias, A_log, p_dtp, p_dAe);
    // 5. SSM scan (both directions)
    scan_kernel<<<2 * BSZn * NHEADSn, 64>>>(p_xbcf, p_xbcb, p_dtp, p_dAe, D_param, p_yf, p_yb);
    // 6. gate + RMSNorm per dir + sum
    gatenorm_kernel<<<BT, 256>>>(p_yf, p_yb, p_zx, norm_w, p_ysum);
    // 7. out_f + out_b = ysum @ out_proj^T  [1024, 768]
    gemm_tc<0><<<dim3(DMODEL / 64, BT / 128), 256>>>(p_ysum, out_proj, nullptr, nullptr, p_mi, BT, DMODEL, DINNER);
    // 8. ln2
    ln_kernel<<<BT, 256>>>(p_mi, ln2_w, ln2_b, p_m);
    // 9. h1 = gelu(m @ ff_w1^T + b1)  [1024, 3072]
    gemm_tc<1><<<dim3(DFF / 64, BT / 128), 256>>>(p_m, ff_w1, ff_b1, nullptr, p_h1, BT, DFF, DMODEL);
    // 10. out = h1 @ ff_w2^T + b2 + x
    gemm_tc<2><<<dim3(DMODEL / 64, BT / 128), 256>>>(p_h1, ff_w2, ff_b2, x, out, BT, DMODEL, DFF);
}